// round 14
// baseline (speedup 1.0000x reference)
#include <cuda_runtime.h>
#include <cuda_bf16.h>

// loss = (1/B) * sum_b sum_{i<j} max(0, (s_i - s_j) + 0.1*(j-i)),  s = scores[argsort(labels)]
// t_k = s_sorted_k - 0.1k  ->  pair term = relu(t_i - t_j) = ((t_i-t_j)+|t_i-t_j|)/2, so
//   sum_{i<j} relu(t_i-t_j) = 0.5*[ sum_k t_k*(63-2k) + sum_m v_m*(2m-63) ],  v = sort(t) asc.
//
// Compute path: byte-exact R5/R13 (best proven). 8 elements/lane, 8 lanes/row,
// 4 rows/warp. Sort #1: labels as order-preserving uint32 keys with embedded 6-bit
// index (stable argsort). Score gather via smem staging. Sort #2: float sort of t.
//
// R14 isolated change: block size 256 -> 128 (GRID 1024 -> 2048). Single-wave SM
// load quantization drops from 7-vs-6 blocks (15% straggler) to 14-vs-13 (7%).

#define BATCH 32768
#define THREADS 128
#define WARPS 4
#define GRID (BATCH / (WARPS * 4))   // 2048 blocks, 4 rows per warp

__device__ float g_partials[GRID];
__device__ unsigned int g_done = 0;

__device__ __forceinline__ float warp_sum(float v) {
#pragma unroll
    for (int o = 16; o; o >>= 1) v += __shfl_xor_sync(0xffffffffu, v, o);
    return v;
}

__device__ __forceinline__ float        tmin(float a, float b)               { return fminf(a, b); }
__device__ __forceinline__ float        tmax(float a, float b)               { return fmaxf(a, b); }
__device__ __forceinline__ unsigned int tmin(unsigned int a, unsigned int b) { return umin(a, b); }
__device__ __forceinline__ unsigned int tmax(unsigned int a, unsigned int b) { return umax(a, b); }

// compile-time direction CEs (2 inst each)
template <class T> __device__ __forceinline__ void ceAsc (T& a, T& b) { const T lo = tmin(a, b); b = tmax(a, b); a = lo; }
template <class T> __device__ __forceinline__ void ceDesc(T& a, T& b) { const T hi = tmax(a, b); b = tmin(a, b); a = hi; }

// runtime-direction CE: conditional swap (SETP + 2 SEL)
template <class T>
__device__ __forceinline__ void ceSwap(T& a, T& b, bool up) {
    const bool sw = ((b < a) == up);
    const T x = a, y = b;
    a = sw ? y : x;
    b = sw ? x : y;
}

// inter-lane step at lane distance ld: keep min iff wm (SHFL + SETP + SEL per reg)
template <class T>
__device__ __forceinline__ void interCE(T v[8], int ld, bool wm) {
#pragma unroll
    for (int s = 0; s < 8; ++s) {
        const T p = __shfl_xor_sync(0xffffffffu, v[s], ld);
        v[s] = ((p < v[s]) == wm) ? p : v[s];
    }
}

// intra-lane merge of a bitonic 8-seq, runtime direction
template <class T>
__device__ __forceinline__ void intra3(T v[8], bool up) {
    ceSwap(v[0], v[4], up); ceSwap(v[1], v[5], up); ceSwap(v[2], v[6], up); ceSwap(v[3], v[7], up);
    ceSwap(v[0], v[2], up); ceSwap(v[1], v[3], up); ceSwap(v[4], v[6], up); ceSwap(v[5], v[7], up);
    ceSwap(v[0], v[1], up); ceSwap(v[2], v[3], up); ceSwap(v[4], v[5], up); ceSwap(v[6], v[7], up);
}

// intra-lane merge, ascending (compile-time, pure min/max)
template <class T>
__device__ __forceinline__ void intra3Asc(T v[8]) {
    ceAsc(v[0], v[4]); ceAsc(v[1], v[5]); ceAsc(v[2], v[6]); ceAsc(v[3], v[7]);
    ceAsc(v[0], v[2]); ceAsc(v[1], v[3]); ceAsc(v[4], v[6]); ceAsc(v[5], v[7]);
    ceAsc(v[0], v[1]); ceAsc(v[2], v[3]); ceAsc(v[4], v[5]); ceAsc(v[6], v[7]);
}

// ascending bitonic sort of 64 elements: idx = 8*lg + slot, lg = lane & 7
template <class T>
__device__ __forceinline__ void bitonic64(T v[8], int lg) {
    // k=2: dir = (idx&2)==0 -> slot-indexed, compile-time
    ceAsc (v[0], v[1]); ceDesc(v[2], v[3]); ceAsc (v[4], v[5]); ceDesc(v[6], v[7]);
    // k=4: dir = (idx&4)==0 -> compile-time; layers d=2, d=1
    ceAsc (v[0], v[2]); ceAsc (v[1], v[3]); ceDesc(v[4], v[6]); ceDesc(v[5], v[7]);
    ceAsc (v[0], v[1]); ceAsc (v[2], v[3]); ceDesc(v[4], v[5]); ceDesc(v[6], v[7]);
    // k=8: dir = (lg&1)==0, fully intra-lane
    { const bool up = (lg & 1) == 0; intra3(v, up); }
    // k=16
    { const bool up = (lg & 2) == 0;
      interCE(v, 1, ((lg & 1) == 0) == up);
      intra3(v, up); }
    // k=32
    { const bool up = (lg & 4) == 0;
      interCE(v, 2, ((lg & 2) == 0) == up);
      interCE(v, 1, ((lg & 1) == 0) == up);
      intra3(v, up); }
    // k=64: ascending everywhere
    { interCE(v, 4, (lg & 4) == 0);
      interCE(v, 2, (lg & 2) == 0);
      interCE(v, 1, (lg & 1) == 0);
      intra3Asc(v); }
}

// order-preserving float -> uint32 (ascending), low 6 bits carry original index
__device__ __forceinline__ unsigned int pack_key(float f, int idx) {
    unsigned int u = __float_as_uint(f);
    u ^= (unsigned int)((int)u >> 31) | 0x80000000u;
    return (u & ~63u) | (unsigned int)idx;
}

__global__ __launch_bounds__(THREADS)
void loss_kernel(const float* __restrict__ scores,
                 const float* __restrict__ labels,
                 float* __restrict__ out) {
    __shared__ float shsc[WARPS][4][68];   // per-(warp,row) score staging, odd stride
    __shared__ float wpart[WARPS];
    __shared__ bool  isLast;

    const int warp = threadIdx.x >> 5;
    const int lane = threadIdx.x & 31;
    const int lg   = lane & 7;            // row-local lane (8 per row)
    const int qtr  = lane >> 3;           // which of the 4 rows in this warp
    const int wg   = blockIdx.x * WARPS + warp;
    const int row  = wg * 4 + qtr;

    // lane owns elements 8lg..8lg+7 of its row (two float4 loads, coalesced)
    const float4 L0 = reinterpret_cast<const float4*>(labels)[row * 16 + 2 * lg];
    const float4 L1 = reinterpret_cast<const float4*>(labels)[row * 16 + 2 * lg + 1];
    const float4 S0 = reinterpret_cast<const float4*>(scores)[row * 16 + 2 * lg];
    const float4 S1 = reinterpret_cast<const float4*>(scores)[row * 16 + 2 * lg + 1];

    // stage scores for post-sort gather
    *reinterpret_cast<float4*>(&shsc[warp][qtr][8 * lg])     = S0;
    *reinterpret_cast<float4*>(&shsc[warp][qtr][8 * lg + 4]) = S1;
    __syncwarp();

    unsigned int key[8];
    key[0] = pack_key(L0.x, 8 * lg + 0);
    key[1] = pack_key(L0.y, 8 * lg + 1);
    key[2] = pack_key(L0.z, 8 * lg + 2);
    key[3] = pack_key(L0.w, 8 * lg + 3);
    key[4] = pack_key(L1.x, 8 * lg + 4);
    key[5] = pack_key(L1.y, 8 * lg + 5);
    key[6] = pack_key(L1.z, 8 * lg + 6);
    key[7] = pack_key(L1.w, 8 * lg + 7);

    bitonic64(key, lg);                   // sort #1: by label (stable via embedded index)

    // gather scores at sorted order; t_p = s_sorted_p - 0.1p, p = 8lg + s
    const float lgf = (float)lg;
    float t[8];
#pragma unroll
    for (int s = 0; s < 8; ++s) {
        const float sv = shsc[warp][qtr][(int)(key[s] & 63u)];
        t[s] = fmaf(-0.8f, lgf, sv) - 0.1f * (float)s;
    }

    // linear term: c_p = 63 - 2p = (63 - 16lg) - 2s
    const float cb = 63.0f - 16.0f * lgf;
    float acc = 0.f;
#pragma unroll
    for (int s = 0; s < 8; ++s) acc = fmaf(t[s], cb - 2.0f * (float)s, acc);

    bitonic64(t, lg);                     // sort #2: values only

    // abs term: sum_m v_m*(2m-63) = -(weighted sum at (63-2m))
    float acc2 = 0.f;
#pragma unroll
    for (int s = 0; s < 8; ++s) acc2 = fmaf(t[s], cb - 2.0f * (float)s, acc2);
    acc -= acc2;

    // ---- deterministic block reduction (lanes cover 4 rows) ----
    const float ws = warp_sum(acc);
    if (lane == 0) wpart[warp] = ws;
    __syncthreads();
    if (warp == 0) {
        float x = (lane < WARPS) ? wpart[lane] : 0.f;
        x = warp_sum(x);
        if (lane == 0) {
            g_partials[blockIdx.x] = x;
            __threadfence();
            isLast = (atomicAdd(&g_done, 1u) == GRID - 1);
        }
    }
    __syncthreads();

    // ---- last block: fixed-order final reduction, reset counter ----
    if (isLast) {
        float x = 0.f;
#pragma unroll
        for (int i = 0; i < GRID / THREADS; ++i)
            x += __ldcg(&g_partials[threadIdx.x + i * THREADS]);
        x = warp_sum(x);
        if (lane == 0) wpart[warp] = x;
        __syncthreads();
        if (warp == 0) {
            float y = (lane < WARPS) ? wpart[lane] : 0.f;
            y = warp_sum(y);
            if (lane == 0) {
                out[0] = y * (0.5f / (float)BATCH);
                g_done = 0;
            }
        }
    }
}

extern "C" void kernel_launch(void* const* d_in, const int* in_sizes, int n_in,
                              void* d_out, int out_size) {
    const float* scores = (const float*)d_in[0];
    const float* labels = (const float*)d_in[1];
    float* out = (float*)d_out;
    loss_kernel<<<GRID, THREADS>>>(scores, labels, out);
}

// round 15
// speedup vs baseline: 1.0368x; 1.0368x over previous
#include <cuda_runtime.h>
#include <cuda_bf16.h>

// loss = (1/B) * sum_b sum_{i<j} max(0, (s_i - s_j) + 0.1*(j-i)),  s = scores[argsort(labels)]
// t_k = s_sorted_k - 0.1k  ->  pair term = relu(t_i - t_j) = ((t_i-t_j)+|t_i-t_j|)/2, so
//   sum_{i<j} relu(t_i-t_j) = 0.5*[ sum_k t_k*(63-2k) + sum_m v_m*(2m-63) ],  v = sort(t) asc.
//
// Final kernel (R15 = best-reproduced config, R14 byte-exact):
//   - 8 elements/lane, 8 lanes/row, 4 rows/warp; 128-thread blocks, 2048 blocks.
//   - Sort #1: labels as order-preserving uint32 keys with embedded 6-bit original
//     index -> exact stable argsort; score gather via smem staging.
//   - Sort #2: keys-only float bitonic sort of t.
//   - Single fused kernel; deterministic fixed-order reduction via last-block pattern
//     (counter self-resets -> graph-replay safe). rel_err 2.1e-7, bit-stable.

#define BATCH 32768
#define THREADS 128
#define WARPS 4
#define GRID (BATCH / (WARPS * 4))   // 2048 blocks, 4 rows per warp

__device__ float g_partials[GRID];
__device__ unsigned int g_done = 0;

__device__ __forceinline__ float warp_sum(float v) {
#pragma unroll
    for (int o = 16; o; o >>= 1) v += __shfl_xor_sync(0xffffffffu, v, o);
    return v;
}

__device__ __forceinline__ float        tmin(float a, float b)               { return fminf(a, b); }
__device__ __forceinline__ float        tmax(float a, float b)               { return fmaxf(a, b); }
__device__ __forceinline__ unsigned int tmin(unsigned int a, unsigned int b) { return umin(a, b); }
__device__ __forceinline__ unsigned int tmax(unsigned int a, unsigned int b) { return umax(a, b); }

// compile-time direction CEs (2 inst each)
template <class T> __device__ __forceinline__ void ceAsc (T& a, T& b) { const T lo = tmin(a, b); b = tmax(a, b); a = lo; }
template <class T> __device__ __forceinline__ void ceDesc(T& a, T& b) { const T hi = tmax(a, b); b = tmin(a, b); a = hi; }

// runtime-direction CE: conditional swap (SETP + 2 SEL)
template <class T>
__device__ __forceinline__ void ceSwap(T& a, T& b, bool up) {
    const bool sw = ((b < a) == up);
    const T x = a, y = b;
    a = sw ? y : x;
    b = sw ? x : y;
}

// inter-lane step at lane distance ld: keep min iff wm (SHFL + SETP + SEL per reg)
template <class T>
__device__ __forceinline__ void interCE(T v[8], int ld, bool wm) {
#pragma unroll
    for (int s = 0; s < 8; ++s) {
        const T p = __shfl_xor_sync(0xffffffffu, v[s], ld);
        v[s] = ((p < v[s]) == wm) ? p : v[s];
    }
}

// intra-lane merge of a bitonic 8-seq, runtime direction
template <class T>
__device__ __forceinline__ void intra3(T v[8], bool up) {
    ceSwap(v[0], v[4], up); ceSwap(v[1], v[5], up); ceSwap(v[2], v[6], up); ceSwap(v[3], v[7], up);
    ceSwap(v[0], v[2], up); ceSwap(v[1], v[3], up); ceSwap(v[4], v[6], up); ceSwap(v[5], v[7], up);
    ceSwap(v[0], v[1], up); ceSwap(v[2], v[3], up); ceSwap(v[4], v[5], up); ceSwap(v[6], v[7], up);
}

// intra-lane merge, ascending (compile-time, pure min/max)
template <class T>
__device__ __forceinline__ void intra3Asc(T v[8]) {
    ceAsc(v[0], v[4]); ceAsc(v[1], v[5]); ceAsc(v[2], v[6]); ceAsc(v[3], v[7]);
    ceAsc(v[0], v[2]); ceAsc(v[1], v[3]); ceAsc(v[4], v[6]); ceAsc(v[5], v[7]);
    ceAsc(v[0], v[1]); ceAsc(v[2], v[3]); ceAsc(v[4], v[5]); ceAsc(v[6], v[7]);
}

// ascending bitonic sort of 64 elements: idx = 8*lg + slot, lg = lane & 7
template <class T>
__device__ __forceinline__ void bitonic64(T v[8], int lg) {
    // k=2: dir = (idx&2)==0 -> slot-indexed, compile-time
    ceAsc (v[0], v[1]); ceDesc(v[2], v[3]); ceAsc (v[4], v[5]); ceDesc(v[6], v[7]);
    // k=4: dir = (idx&4)==0 -> compile-time; layers d=2, d=1
    ceAsc (v[0], v[2]); ceAsc (v[1], v[3]); ceDesc(v[4], v[6]); ceDesc(v[5], v[7]);
    ceAsc (v[0], v[1]); ceAsc (v[2], v[3]); ceDesc(v[4], v[5]); ceDesc(v[6], v[7]);
    // k=8: dir = (lg&1)==0, fully intra-lane
    { const bool up = (lg & 1) == 0; intra3(v, up); }
    // k=16
    { const bool up = (lg & 2) == 0;
      interCE(v, 1, ((lg & 1) == 0) == up);
      intra3(v, up); }
    // k=32
    { const bool up = (lg & 4) == 0;
      interCE(v, 2, ((lg & 2) == 0) == up);
      interCE(v, 1, ((lg & 1) == 0) == up);
      intra3(v, up); }
    // k=64: ascending everywhere
    { interCE(v, 4, (lg & 4) == 0);
      interCE(v, 2, (lg & 2) == 0);
      interCE(v, 1, (lg & 1) == 0);
      intra3Asc(v); }
}

// order-preserving float -> uint32 (ascending), low 6 bits carry original index
__device__ __forceinline__ unsigned int pack_key(float f, int idx) {
    unsigned int u = __float_as_uint(f);
    u ^= (unsigned int)((int)u >> 31) | 0x80000000u;
    return (u & ~63u) | (unsigned int)idx;
}

__global__ __launch_bounds__(THREADS)
void loss_kernel(const float* __restrict__ scores,
                 const float* __restrict__ labels,
                 float* __restrict__ out) {
    __shared__ float shsc[WARPS][4][68];   // per-(warp,row) score staging, odd stride
    __shared__ float wpart[WARPS];
    __shared__ bool  isLast;

    const int warp = threadIdx.x >> 5;
    const int lane = threadIdx.x & 31;
    const int lg   = lane & 7;            // row-local lane (8 per row)
    const int qtr  = lane >> 3;           // which of the 4 rows in this warp
    const int wg   = blockIdx.x * WARPS + warp;
    const int row  = wg * 4 + qtr;

    // lane owns elements 8lg..8lg+7 of its row (two float4 loads, coalesced)
    const float4 L0 = reinterpret_cast<const float4*>(labels)[row * 16 + 2 * lg];
    const float4 L1 = reinterpret_cast<const float4*>(labels)[row * 16 + 2 * lg + 1];
    const float4 S0 = reinterpret_cast<const float4*>(scores)[row * 16 + 2 * lg];
    const float4 S1 = reinterpret_cast<const float4*>(scores)[row * 16 + 2 * lg + 1];

    // stage scores for post-sort gather
    *reinterpret_cast<float4*>(&shsc[warp][qtr][8 * lg])     = S0;
    *reinterpret_cast<float4*>(&shsc[warp][qtr][8 * lg + 4]) = S1;
    __syncwarp();

    unsigned int key[8];
    key[0] = pack_key(L0.x, 8 * lg + 0);
    key[1] = pack_key(L0.y, 8 * lg + 1);
    key[2] = pack_key(L0.z, 8 * lg + 2);
    key[3] = pack_key(L0.w, 8 * lg + 3);
    key[4] = pack_key(L1.x, 8 * lg + 4);
    key[5] = pack_key(L1.y, 8 * lg + 5);
    key[6] = pack_key(L1.z, 8 * lg + 6);
    key[7] = pack_key(L1.w, 8 * lg + 7);

    bitonic64(key, lg);                   // sort #1: by label (stable via embedded index)

    // gather scores at sorted order; t_p = s_sorted_p - 0.1p, p = 8lg + s
    const float lgf = (float)lg;
    float t[8];
#pragma unroll
    for (int s = 0; s < 8; ++s) {
        const float sv = shsc[warp][qtr][(int)(key[s] & 63u)];
        t[s] = fmaf(-0.8f, lgf, sv) - 0.1f * (float)s;
    }

    // linear term: c_p = 63 - 2p = (63 - 16lg) - 2s
    const float cb = 63.0f - 16.0f * lgf;
    float acc = 0.f;
#pragma unroll
    for (int s = 0; s < 8; ++s) acc = fmaf(t[s], cb - 2.0f * (float)s, acc);

    bitonic64(t, lg);                     // sort #2: values only

    // abs term: sum_m v_m*(2m-63) = -(weighted sum at (63-2m))
    float acc2 = 0.f;
#pragma unroll
    for (int s = 0; s < 8; ++s) acc2 = fmaf(t[s], cb - 2.0f * (float)s, acc2);
    acc -= acc2;

    // ---- deterministic block reduction (lanes cover 4 rows) ----
    const float ws = warp_sum(acc);
    if (lane == 0) wpart[warp] = ws;
    __syncthreads();
    if (warp == 0) {
        float x = (lane < WARPS) ? wpart[lane] : 0.f;
        x = warp_sum(x);
        if (lane == 0) {
            g_partials[blockIdx.x] = x;
            __threadfence();
            isLast = (atomicAdd(&g_done, 1u) == GRID - 1);
        }
    }
    __syncthreads();

    // ---- last block: fixed-order final reduction, reset counter ----
    if (isLast) {
        float x = 0.f;
#pragma unroll
        for (int i = 0; i < GRID / THREADS; ++i)
            x += __ldcg(&g_partials[threadIdx.x + i * THREADS]);
        x = warp_sum(x);
        if (lane == 0) wpart[warp] = x;
        __syncthreads();
        if (warp == 0) {
            float y = (lane < WARPS) ? wpart[lane] : 0.f;
            y = warp_sum(y);
            if (lane == 0) {
                out[0] = y * (0.5f / (float)BATCH);
                g_done = 0;
            }
        }
    }
}

extern "C" void kernel_launch(void* const* d_in, const int* in_sizes, int n_in,
                              void* d_out, int out_size) {
    const float* scores = (const float*)d_in[0];
    const float* labels = (const float*)d_in[1];
    float* out = (float*)d_out;
    loss_kernel<<<GRID, THREADS>>>(scores, labels, out);
}